// round 1
// baseline (speedup 1.0000x reference)
#include <cuda_runtime.h>

// CapsNet dynamic routing, persistent-kernel formulation.
// B=512 batch, K=1152 input caps (8-dim), J=10 output caps (16-dim), 3 routing iters.
//
// 144 CTAs, each owns KL=8 k-values. u_hat[b, k-slice, u] (512x8x16 fp32) is kept
// on-chip: 384 b's in SMEM, 128 b's in registers (32 regs/thread). Rebuilt once per j.
// Per routing iteration:
//   phase1: per-CTA partial s over its 8 k's  -> g_spart   (grid barrier)
//   phase2: CTAs 0..127 reduce 144 partials, squash -> g_v (grid barrier)
//   phase3: agree[k], b_IJ row update, softmax -> c  (all CTA-local, no barrier)
// b_IJ rows live entirely in SMEM of the owning CTA.

#define NCTA 144
#define THREADS 512
#define KL 8            // k's per CTA
#define BATCH 512
#define UDIM 16
#define DDIM 8
#define JOUT 10
#define ITERS 3
#define SB 384          // b's with u_hat in smem
#define RQ 4            // (512-384)/32 register chunks
#define SQ 12           // 384/32 smem chunks
#define UHB 136         // padded floats per b in uh_s (128 + 8, kills bank conflicts)
#define XSB 68          // padded floats per b in xs   (64 + 4)

#define SMEM_FLOATS (SB*UHB + 32*XSB + KL*DDIM*UDIM + KL*JOUT + KL + 16*KL + 4*16*8)
#define SMEM_BYTES (SMEM_FLOATS * 4)

__device__ float g_spart[NCTA * BATCH * UDIM];  // per-CTA partial s
__device__ float g_v[BATCH * UDIM];             // squashed v
__device__ unsigned g_bar;                      // grid barrier counter (reset at kernel end)

__device__ __forceinline__ void grid_barrier(unsigned target) {
    __syncthreads();
    if (threadIdx.x == 0) {
        __threadfence();                  // release prior global writes
        atomicAdd(&g_bar, 1u);
        volatile unsigned* p = &g_bar;
        while (*p < target) __nanosleep(64);
        __threadfence();                  // acquire
    }
    __syncthreads();
}

__global__ void __launch_bounds__(THREADS, 1)
caps_routing_kernel(const float* __restrict__ x,   // [512,1152,8]
                    const float* __restrict__ W,   // [10,1152,8,16]
                    float* __restrict__ out)       // [512,10,16]
{
    extern __shared__ float sm[];
    float* uh_s  = sm;                      // SB*UHB
    float* xs    = uh_s + SB * UHB;         // 32*XSB staging for x
    float* w_s   = xs + 32 * XSB;           // KL*8*16 = 1024
    float* bs    = w_s + KL * DDIM * UDIM;  // KL*10 b_IJ rows
    float* c_s   = bs + KL * JOUT;          // KL coupling coeffs (this CTA's k's)
    float* wred  = c_s + KL;                // 16 warps x 8
    float* p2red = wred + 16 * KL;          // 4*16*8 phase-2 reduction

    const int t    = threadIdx.x;
    const int cta  = blockIdx.x;
    const int k0   = cta * KL;
    const int u    = t & 15;
    const int bg   = t >> 4;       // 0..31
    const int lane = t & 31;
    const int warp = t >> 5;

    float uhr[RQ][KL];             // register-resident u_hat for b in [384,512)

    // init b_IJ rows (zero) and initial c = softmax(0) = 1/10
    for (int i = t; i < KL * JOUT; i += THREADS) bs[i] = 0.f;
    if (t < KL) c_s[t] = 0.1f;
    __syncthreads();

    unsigned epoch = 0;

    for (int j = 0; j < JOUT; ++j) {
        // ---- load W slice for (j, k0..k0+7): 1024 contiguous-per-k floats ----
        #pragma unroll
        for (int r = 0; r < 2; ++r) {
            int f = t + r * THREADS;
            int kl = f >> 7, rest = f & 127;
            w_s[f] = W[(size_t)((j * 1152) + k0 + kl) * 128 + rest];
        }
        __syncthreads();

        // ---- build u_hat: 16 chunks of 32 b's ----
        #pragma unroll
        for (int ch = 0; ch < SQ + RQ; ++ch) {
            const int bc = ch * 32;
            // stage x[bc..bc+31, k0..k0+7, 0..7] : one float4 per thread
            {
                const float4 v4 = *reinterpret_cast<const float4*>(
                    x + ((size_t)(bc + bg) * 1152 + k0) * 8 + u * 4);
                float* dst = xs + bg * XSB + u * 4;
                dst[0] = v4.x; dst[1] = v4.y; dst[2] = v4.z; dst[3] = v4.w;
            }
            __syncthreads();
            if (ch < SQ) {
                #pragma unroll
                for (int kl = 0; kl < KL; ++kl) {
                    float acc = 0.f;
                    #pragma unroll
                    for (int d = 0; d < DDIM; ++d)
                        acc = fmaf(xs[bg * XSB + kl * 8 + d],
                                   w_s[(kl * 8 + d) * 16 + u], acc);
                    uh_s[(bc + bg) * UHB + kl * 16 + u] = acc;
                }
            } else {
                const int q = ch - SQ;
                #pragma unroll
                for (int kl = 0; kl < KL; ++kl) {
                    float acc = 0.f;
                    #pragma unroll
                    for (int d = 0; d < DDIM; ++d)
                        acc = fmaf(xs[bg * XSB + kl * 8 + d],
                                   w_s[(kl * 8 + d) * 16 + u], acc);
                    uhr[q][kl] = acc;
                }
            }
            __syncthreads();
        }

        for (int it = 0; it < ITERS; ++it) {
            // ---------- phase 1: partial s over this CTA's 8 k's ----------
            {
                float c0[KL];
                #pragma unroll
                for (int kl = 0; kl < KL; ++kl) c0[kl] = c_s[kl];
                #pragma unroll
                for (int q = 0; q < SQ; ++q) {
                    const int b = q * 32 + bg;
                    float acc = 0.f;
                    #pragma unroll
                    for (int kl = 0; kl < KL; ++kl)
                        acc = fmaf(c0[kl], uh_s[b * UHB + kl * 16 + u], acc);
                    __stcg(&g_spart[(cta * BATCH + b) * UDIM + u], acc);
                }
                #pragma unroll
                for (int q = 0; q < RQ; ++q) {
                    const int b = SB + q * 32 + bg;
                    float acc = 0.f;
                    #pragma unroll
                    for (int kl = 0; kl < KL; ++kl)
                        acc = fmaf(c0[kl], uhr[q][kl], acc);
                    __stcg(&g_spart[(cta * BATCH + b) * UDIM + u], acc);
                }
            }
            ++epoch; grid_barrier(epoch * NCTA);

            // ---------- phase 2: reduce partials, squash -> v ----------
            if (cta < 128) {
                const int bl = (t >> 4) & 3;
                const int ch = t >> 6;            // 0..7
                const int b  = cta * 4 + bl;
                float p = 0.f;
                for (int i = ch; i < NCTA; i += 8)
                    p += __ldcg(&g_spart[(i * BATCH + b) * UDIM + u]);
                p2red[(bl * 16 + u) * 8 + ch] = p;
                __syncthreads();
                if (t < 64) {
                    float s = 0.f;
                    #pragma unroll
                    for (int c2 = 0; c2 < 8; ++c2) s += p2red[t * 8 + c2];
                    float sq = s * s;
                    #pragma unroll
                    for (int m = 8; m >= 1; m >>= 1)
                        sq += __shfl_xor_sync(0xffffffffu, sq, m);
                    const float v = s * sq / ((1.f + sq) * (sqrtf(sq) + 1e-7f));
                    const int bb = cta * 4 + (t >> 4);
                    __stcg(&g_v[bb * 16 + (t & 15)], v);
                    if (it == ITERS - 1)
                        out[((size_t)bb * JOUT + j) * UDIM + (t & 15)] = v;
                }
            }
            ++epoch; grid_barrier(epoch * NCTA);

            // ---------- phase 3: agree, b_IJ update, next c (CTA-local) ----------
            {
                float ag[KL];
                #pragma unroll
                for (int kl = 0; kl < KL; ++kl) ag[kl] = 0.f;
                #pragma unroll
                for (int q = 0; q < SQ; ++q) {
                    const int b = q * 32 + bg;
                    const float vv = __ldcg(&g_v[b * UDIM + u]);
                    #pragma unroll
                    for (int kl = 0; kl < KL; ++kl)
                        ag[kl] = fmaf(vv, uh_s[b * UHB + kl * 16 + u], ag[kl]);
                }
                #pragma unroll
                for (int q = 0; q < RQ; ++q) {
                    const int b = SB + q * 32 + bg;
                    const float vv = __ldcg(&g_v[b * UDIM + u]);
                    #pragma unroll
                    for (int kl = 0; kl < KL; ++kl)
                        ag[kl] = fmaf(vv, uhr[q][kl], ag[kl]);
                }
                #pragma unroll
                for (int kl = 0; kl < KL; ++kl) {
                    float v = ag[kl];
                    #pragma unroll
                    for (int m = 16; m >= 1; m >>= 1)
                        v += __shfl_xor_sync(0xffffffffu, v, m);
                    if (lane == 0) wred[warp * KL + kl] = v;
                }
                __syncthreads();
                if (t < KL) {
                    float s = 0.f;
                    #pragma unroll
                    for (int w2 = 0; w2 < 16; ++w2) s += wred[w2 * KL + t];
                    bs[t * JOUT + j] += s;
                    const int jn = (it < ITERS - 1) ? j : j + 1;
                    if (jn < JOUT) {
                        float m = bs[t * JOUT];
                        #pragma unroll
                        for (int jj = 1; jj < JOUT; ++jj)
                            m = fmaxf(m, bs[t * JOUT + jj]);
                        float den = 0.f, num = 0.f;
                        #pragma unroll
                        for (int jj = 0; jj < JOUT; ++jj) {
                            const float e = expf(bs[t * JOUT + jj] - m);
                            den += e;
                            if (jj == jn) num = e;
                        }
                        c_s[t] = num / den;
                    }
                }
                __syncthreads();
            }
        } // it
    } // j

    // final barrier + counter reset so the next (graph-replayed) launch starts clean
    ++epoch; grid_barrier(epoch * NCTA);
    if (cta == 0 && t == 0) *((volatile unsigned*)&g_bar) = 0u;
}

extern "C" void kernel_launch(void* const* d_in, const int* in_sizes, int n_in,
                              void* d_out, int out_size) {
    const float* x = (const float*)d_in[0];   // [512,1152,8,1]
    const float* W = (const float*)d_in[1];   // [10,1152,8,16]
    float* out = (float*)d_out;               // [512,10,16,1]
    (void)in_sizes; (void)n_in; (void)out_size;

    cudaFuncSetAttribute(caps_routing_kernel,
                         cudaFuncAttributeMaxDynamicSharedMemorySize, SMEM_BYTES);
    caps_routing_kernel<<<NCTA, THREADS, SMEM_BYTES>>>(x, W, out);
}

// round 2
// speedup vs baseline: 1.2172x; 1.2172x over previous
#include <cuda_runtime.h>

// CapsNet dynamic routing, persistent kernel, round 2.
// 144 CTAs x 1024 threads. Each CTA owns KL=8 k's. u_hat (thread-private slices):
// 384 b's in smem (swizzled float4 rows), 128 b's in registers (f32x2-packed).
// W quarter-slices cached in registers during the build. All inner FMA via fma.rn.f32x2.
// Sense-reversing grid barrier (no reset needed, graph-replay safe).

#define NCTA 144
#define THREADS 1024
#define KL 8
#define BATCH 512
#define JOUT 10
#define ITERS 3
#define SB 384          // b's with u_hat in smem
#define SQ 6            // smem chunks of 64 b
#define RQ 2            // register chunks of 64 b
#define UHB 128         // floats per b row (swizzled, no pad needed)
#define XSB2 48         // xs row stride (16 used + pad, conflict-free)
#define WTB 68          // w_t row stride

#define SMEM_FLOATS (SB*UHB + 64*XSB2 + 16*WTB + KL*JOUT + KL + 1024)
#define SMEM_BYTES (SMEM_FLOATS * 4)

typedef unsigned long long ull;

__device__ float g_spart[NCTA * BATCH * 16];
__device__ float g_v[BATCH * 16];
__device__ unsigned g_count;
__device__ volatile unsigned g_sense;

__device__ __forceinline__ ull f2_pk(float lo, float hi) {
    ull r; asm("mov.b64 %0,{%1,%2};" : "=l"(r) : "f"(lo), "f"(hi)); return r;
}
__device__ __forceinline__ float2 f2_up(ull a) {
    float2 r; asm("mov.b64 {%0,%1},%2;" : "=f"(r.x), "=f"(r.y) : "l"(a)); return r;
}
__device__ __forceinline__ ull f2_fma(ull a, ull b, ull c) {
    ull d; asm("fma.rn.f32x2 %0,%1,%2,%3;" : "=l"(d) : "l"(a), "l"(b), "l"(c)); return d;
}
__device__ __forceinline__ ull f2_mul(ull a, ull b) {
    ull d; asm("mul.rn.f32x2 %0,%1,%2;" : "=l"(d) : "l"(a), "l"(b)); return d;
}
__device__ __forceinline__ ull f2_add(ull a, ull b) {
    ull d; asm("add.rn.f32x2 %0,%1,%2;" : "=l"(d) : "l"(a), "l"(b)); return d;
}

// swizzled word offset of the h-th float4 (h=0: kl0-3, h=1: kl4-7) for vector idx u
__device__ __forceinline__ int uoff(int u, int h) { return (u * 8 + h * 4) ^ (u & 4); }

__device__ __forceinline__ void grid_barrier() {
    __syncthreads();
    if (threadIdx.x == 0) {
        __threadfence();                      // release
        const unsigned gen = g_sense;
        const unsigned old = atomicAdd(&g_count, 1u);
        if (old == NCTA - 1) {
            g_count = 0;                      // safe: all arrivals done, spinners gated by sense
            __threadfence();
            g_sense = gen + 1;
        } else {
            while (g_sense == gen) __nanosleep(64);
        }
        __threadfence();                      // acquire
    }
    __syncthreads();
}

__global__ void __launch_bounds__(THREADS, 1)
caps_routing_kernel(const float* __restrict__ x,   // [512,1152,8]
                    const float* __restrict__ W,   // [10,1152,8,16]
                    float* __restrict__ out)       // [512,10,16]
{
    extern __shared__ float sm[];
    float* uh_s    = sm;                     // SB*UHB
    float* xs      = uh_s + SB * UHB;        // 64*XSB2
    float* w_t     = xs + 64 * XSB2;         // 16*WTB : w_t[u][kl*8+d]
    float* bs      = w_t + 16 * WTB;         // KL*JOUT b_IJ rows
    float* c_s     = bs + KL * JOUT;         // KL coupling coeffs
    float* scratch = c_s + KL;               // 1024 (phase2 + phase3 reductions)

    const int t    = threadIdx.x;
    const int cta  = blockIdx.x;
    const int k0   = cta * KL;
    const int u    = t & 15;
    const int bg   = t >> 4;                 // 0..63
    const int lane = t & 31;
    const int warp = t >> 5;

    ull uhr[RQ][4];                          // register u_hat for b in [384,512): (kl pairs)

    for (int i = t; i < KL * JOUT; i += THREADS) bs[i] = 0.f;
    if (t < KL) c_s[t] = 0.1f;               // softmax(0) over 10
    __syncthreads();

    for (int j = 0; j < JOUT; ++j) {
        // ---- W[j, k0+kl, d, uu] -> w_t[uu][kl*8+d] (transposed, u-major) ----
        {
            const int kl = t >> 7, rest = t & 127;
            const int d = rest >> 4, uu = rest & 15;
            w_t[uu * WTB + kl * 8 + d] = W[(size_t)(j * 1152 + k0 + kl) * 128 + rest];
        }
        __syncthreads();

        // ---- build u_hat: quarters of kl (W quarter in registers), chunks of 64 b ----
        #pragma unroll
        for (int qi = 0; qi < 4; ++qi) {
            ulonglong2 Wq0a, Wq0b, Wq1a, Wq1b;   // 2 kl x 8 d, f32x2-packed
            Wq0a = *reinterpret_cast<const ulonglong2*>(w_t + u * WTB + (qi * 2 + 0) * 8);
            Wq0b = *reinterpret_cast<const ulonglong2*>(w_t + u * WTB + (qi * 2 + 0) * 8 + 4);
            Wq1a = *reinterpret_cast<const ulonglong2*>(w_t + u * WTB + (qi * 2 + 1) * 8);
            Wq1b = *reinterpret_cast<const ulonglong2*>(w_t + u * WTB + (qi * 2 + 1) * 8 + 4);

            #pragma unroll
            for (int ch = 0; ch < SQ + RQ; ++ch) {
                const int b = ch * 64 + bg;
                // stage 16 floats of x row (2 kl x 8 d) via one scalar load per thread
                const float xv = x[((size_t)b * 1152 + k0) * 8 + qi * 16 + u];
                __syncwarp();                      // prior chunk's reads done
                xs[bg * XSB2 + u] = xv;
                __syncwarp();

                float a0, a1;
                {
                    const ulonglong2 X0 = *reinterpret_cast<const ulonglong2*>(xs + bg * XSB2);
                    const ulonglong2 X1 = *reinterpret_cast<const ulonglong2*>(xs + bg * XSB2 + 4);
                    ull acc = f2_mul(X0.x, Wq0a.x);
                    acc = f2_fma(X0.y, Wq0a.y, acc);
                    acc = f2_fma(X1.x, Wq0b.x, acc);
                    acc = f2_fma(X1.y, Wq0b.y, acc);
                    const float2 p = f2_up(acc);
                    a0 = p.x + p.y;
                }
                {
                    const ulonglong2 X0 = *reinterpret_cast<const ulonglong2*>(xs + bg * XSB2 + 8);
                    const ulonglong2 X1 = *reinterpret_cast<const ulonglong2*>(xs + bg * XSB2 + 12);
                    ull acc = f2_mul(X0.x, Wq1a.x);
                    acc = f2_fma(X0.y, Wq1a.y, acc);
                    acc = f2_fma(X1.x, Wq1b.x, acc);
                    acc = f2_fma(X1.y, Wq1b.y, acc);
                    const float2 p = f2_up(acc);
                    a1 = p.x + p.y;
                }
                if (ch < SQ) {
                    const int off = (u * 8 + qi * 2) ^ (u & 4);
                    *reinterpret_cast<float2*>(uh_s + b * UHB + off) = make_float2(a0, a1);
                } else {
                    uhr[ch - SQ][qi] = f2_pk(a0, a1);
                }
            }
        }
        __syncwarp();

        for (int it = 0; it < ITERS; ++it) {
            // ---------- phase 1: partial s over this CTA's 8 k's ----------
            {
                const ull c01 = f2_pk(c_s[0], c_s[1]);
                const ull c23 = f2_pk(c_s[2], c_s[3]);
                const ull c45 = f2_pk(c_s[4], c_s[5]);
                const ull c67 = f2_pk(c_s[6], c_s[7]);
                #pragma unroll
                for (int q = 0; q < SQ; ++q) {
                    const int b = q * 64 + bg;
                    const float* src = uh_s + b * UHB;
                    const ulonglong2 A  = *reinterpret_cast<const ulonglong2*>(src + uoff(u, 0));
                    const ulonglong2 Bv = *reinterpret_cast<const ulonglong2*>(src + uoff(u, 1));
                    ull s0 = f2_mul(A.x, c01);
                    ull s1 = f2_mul(A.y, c23);
                    s0 = f2_fma(Bv.x, c45, s0);
                    s1 = f2_fma(Bv.y, c67, s1);
                    const float2 p = f2_up(f2_add(s0, s1));
                    __stcg(&g_spart[((size_t)cta * BATCH + b) * 16 + u], p.x + p.y);
                }
                #pragma unroll
                for (int q = 0; q < RQ; ++q) {
                    const int b = SB + q * 64 + bg;
                    ull s0 = f2_mul(uhr[q][0], c01);
                    ull s1 = f2_mul(uhr[q][1], c23);
                    s0 = f2_fma(uhr[q][2], c45, s0);
                    s1 = f2_fma(uhr[q][3], c67, s1);
                    const float2 p = f2_up(f2_add(s0, s1));
                    __stcg(&g_spart[((size_t)cta * BATCH + b) * 16 + u], p.x + p.y);
                }
            }
            grid_barrier();

            // ---------- phase 2: reduce 144 partials, squash -> v ----------
            if (cta < 128) {
                const int bl  = (t >> 4) & 3;
                const int ch2 = t >> 6;                     // 0..15
                const int b   = cta * 4 + bl;
                float p = 0.f;
                for (int i = ch2; i < NCTA; i += 16)
                    p += __ldcg(&g_spart[((size_t)i * BATCH + b) * 16 + u]);
                scratch[ch2 * 64 + bl * 16 + u] = p;
                __syncthreads();
                if (t < 64) {
                    float s = 0.f;
                    #pragma unroll
                    for (int c2 = 0; c2 < 16; ++c2) s += scratch[c2 * 64 + t];
                    float sq = s * s;
                    #pragma unroll
                    for (int m = 8; m >= 1; m >>= 1)
                        sq += __shfl_xor_sync(0xffffffffu, sq, m);
                    const float v = s * sq / ((1.f + sq) * (sqrtf(sq) + 1e-7f));
                    const int bb = cta * 4 + (t >> 4);
                    __stcg(&g_v[bb * 16 + (t & 15)], v);
                    if (it == ITERS - 1)
                        out[((size_t)bb * JOUT + j) * 16 + (t & 15)] = v;
                }
            }
            grid_barrier();

            // ---------- phase 3: agree, b_IJ update, next c (CTA-local) ----------
            {
                ull ag0 = 0ull, ag1 = 0ull, ag2 = 0ull, ag3 = 0ull;
                #pragma unroll
                for (int q = 0; q < SQ; ++q) {
                    const int b = q * 64 + bg;
                    const float vv = __ldcg(&g_v[b * 16 + u]);
                    const ull vp = f2_pk(vv, vv);
                    const float* src = uh_s + b * UHB;
                    const ulonglong2 A  = *reinterpret_cast<const ulonglong2*>(src + uoff(u, 0));
                    const ulonglong2 Bv = *reinterpret_cast<const ulonglong2*>(src + uoff(u, 1));
                    ag0 = f2_fma(A.x,  vp, ag0);
                    ag1 = f2_fma(A.y,  vp, ag1);
                    ag2 = f2_fma(Bv.x, vp, ag2);
                    ag3 = f2_fma(Bv.y, vp, ag3);
                }
                #pragma unroll
                for (int q = 0; q < RQ; ++q) {
                    const int b = SB + q * 64 + bg;
                    const float vv = __ldcg(&g_v[b * 16 + u]);
                    const ull vp = f2_pk(vv, vv);
                    ag0 = f2_fma(uhr[q][0], vp, ag0);
                    ag1 = f2_fma(uhr[q][1], vp, ag1);
                    ag2 = f2_fma(uhr[q][2], vp, ag2);
                    ag3 = f2_fma(uhr[q][3], vp, ag3);
                }
                float ag[8];
                { float2 p;
                  p = f2_up(ag0); ag[0] = p.x; ag[1] = p.y;
                  p = f2_up(ag1); ag[2] = p.x; ag[3] = p.y;
                  p = f2_up(ag2); ag[4] = p.x; ag[5] = p.y;
                  p = f2_up(ag3); ag[6] = p.x; ag[7] = p.y; }
                #pragma unroll
                for (int kl = 0; kl < KL; ++kl) {
                    float v = ag[kl];
                    #pragma unroll
                    for (int m = 16; m >= 1; m >>= 1)
                        v += __shfl_xor_sync(0xffffffffu, v, m);
                    if (lane == 0) scratch[warp * KL + kl] = v;
                }
                __syncthreads();
                if (t < KL) {
                    float s = 0.f;
                    #pragma unroll
                    for (int w2 = 0; w2 < 32; ++w2) s += scratch[w2 * KL + t];
                    bs[t * JOUT + j] += s;
                    const int jn = (it < ITERS - 1) ? j : j + 1;
                    if (jn < JOUT) {
                        float m = bs[t * JOUT];
                        #pragma unroll
                        for (int jj = 1; jj < JOUT; ++jj)
                            m = fmaxf(m, bs[t * JOUT + jj]);
                        float den = 0.f, num = 0.f;
                        #pragma unroll
                        for (int jj = 0; jj < JOUT; ++jj) {
                            const float e = expf(bs[t * JOUT + jj] - m);
                            den += e;
                            if (jj == jn) num = e;
                        }
                        c_s[t] = num / den;
                    }
                }
                __syncthreads();
            }
        } // it
    } // j
    // sense-reversing barrier needs no end-of-kernel reset: g_count returns to 0
    // after every barrier, g_sense is monotonic and re-read each launch.
}

extern "C" void kernel_launch(void* const* d_in, const int* in_sizes, int n_in,
                              void* d_out, int out_size) {
    const float* x = (const float*)d_in[0];   // [512,1152,8,1]
    const float* W = (const float*)d_in[1];   // [10,1152,8,16]
    float* out = (float*)d_out;               // [512,10,16,1]
    (void)in_sizes; (void)n_in; (void)out_size;

    cudaFuncSetAttribute(caps_routing_kernel,
                         cudaFuncAttributeMaxDynamicSharedMemorySize, SMEM_BYTES);
    caps_routing_kernel<<<NCTA, THREADS, SMEM_BYTES>>>(x, W, out);
}